// round 7
// baseline (speedup 1.0000x reference)
#include <cuda_runtime.h>
#include <cuda_bf16.h>
#include <cstdint>
#include <cstddef>

#define S_LEN 2048
#define HID   2048
#define NH    16
#define HD    128
#define BATCH 2
#define MROWS (BATCH * S_LEN)

// ---------------------------------------------------------------------------
// Scratch (allocation-free rule: device globals)
// ---------------------------------------------------------------------------
__device__ float g_q [(size_t)MROWS * HID];
__device__ float g_k [(size_t)MROWS * HID];
__device__ float g_v [(size_t)MROWS * HID];
__device__ float g_ao[(size_t)MROWS * HID];

__device__ __nv_bfloat16 g_qhi[(size_t)MROWS * HID];
__device__ __nv_bfloat16 g_qlo[(size_t)MROWS * HID];
__device__ __nv_bfloat16 g_khi[(size_t)MROWS * HID];
__device__ __nv_bfloat16 g_klo[(size_t)MROWS * HID];
__device__ __nv_bfloat16 g_vhi[(size_t)MROWS * HID];
__device__ __nv_bfloat16 g_vlo[(size_t)MROWS * HID];

// ---------------------------------------------------------------------------
// helpers
// ---------------------------------------------------------------------------
__device__ __forceinline__ uint32_t smem_u32(const void* p) {
  uint32_t a;
  asm("{ .reg .u64 t; cvta.to.shared.u64 t, %1; cvt.u32.u64 %0, t; }"
      : "=r"(a) : "l"(p));
  return a;
}

__device__ __forceinline__ void ldsm4(uint32_t addr, uint32_t& r0, uint32_t& r1,
                                      uint32_t& r2, uint32_t& r3) {
  asm volatile("ldmatrix.sync.aligned.m8n8.x4.shared.b16 {%0,%1,%2,%3}, [%4];"
               : "=r"(r0), "=r"(r1), "=r"(r2), "=r"(r3) : "r"(addr));
}

__device__ __forceinline__ void ldsm4t(uint32_t addr, uint32_t& r0, uint32_t& r1,
                                       uint32_t& r2, uint32_t& r3) {
  asm volatile("ldmatrix.sync.aligned.m8n8.x4.trans.shared.b16 {%0,%1,%2,%3}, [%4];"
               : "=r"(r0), "=r"(r1), "=r"(r2), "=r"(r3) : "r"(addr));
}

__device__ __forceinline__ void mma16816(float* d, const uint32_t* a,
                                         const uint32_t* b) {
  asm volatile(
      "mma.sync.aligned.m16n8k16.row.col.f32.bf16.bf16.f32 "
      "{%0,%1,%2,%3}, {%4,%5,%6,%7}, {%8,%9}, {%0,%1,%2,%3};"
      : "+f"(d[0]), "+f"(d[1]), "+f"(d[2]), "+f"(d[3])
      : "r"(a[0]), "r"(a[1]), "r"(a[2]), "r"(a[3]), "r"(b[0]), "r"(b[1]));
}

__device__ __forceinline__ void mma1688_tf32(float* d, const uint32_t* a,
                                             const uint32_t* b) {
  asm volatile(
      "mma.sync.aligned.m16n8k8.row.col.f32.tf32.tf32.f32 "
      "{%0,%1,%2,%3}, {%4,%5,%6,%7}, {%8,%9}, {%0,%1,%2,%3};"
      : "+f"(d[0]), "+f"(d[1]), "+f"(d[2]), "+f"(d[3])
      : "r"(a[0]), "r"(a[1]), "r"(a[2]), "r"(a[3]), "r"(b[0]), "r"(b[1]));
}

__device__ __forceinline__ uint32_t f2tf32(float x) {
  uint32_t r;
  asm("cvt.rna.tf32.f32 %0, %1;" : "=r"(r) : "f"(x));
  return r;
}

#define CP_ASYNC16(saddr, gaddr) \
  asm volatile("cp.async.cg.shared.global [%0], [%1], 16;" \
               :: "r"(saddr), "l"(gaddr))
#define CP_COMMIT() asm volatile("cp.async.commit_group;")
#define CP_WAIT1()  asm volatile("cp.async.wait_group 1;")
#define CP_WAIT0()  asm volatile("cp.async.wait_group 0;")

// FFMA-only exp2 (no MUFU): magic-round + degree-6 Taylor, |err| < 2e-7.
__device__ __forceinline__ float exp2p(float x) {
  x = fmaxf(x, -126.f);
  float r = x + 12582912.f;
  int   e = __float_as_int(r) - 0x4B400000;
  float f = x - (r - 12582912.f);
  float p = 1.5403e-4f;
  p = fmaf(p, f, 1.3333558e-3f);
  p = fmaf(p, f, 9.6181291e-3f);
  p = fmaf(p, f, 5.5504109e-2f);
  p = fmaf(p, f, 2.4022651e-1f);
  p = fmaf(p, f, 6.9314718e-1f);
  p = fmaf(p, f, 1.0f);
  return __int_as_float(__float_as_int(p) + (e << 23));
}

__device__ __forceinline__ uint32_t pack_bf16(float x, float y) {
  __nv_bfloat162 t = __floats2bfloat162_rn(x, y);
  return *(uint32_t*)&t;
}

// ---------------------------------------------------------------------------
// fp32 -> bf16 hi/lo split (used for V)
// ---------------------------------------------------------------------------
__global__ void cvt_split(const float* __restrict__ in,
                          __nv_bfloat16* __restrict__ hi,
                          __nv_bfloat16* __restrict__ lo, int n) {
  int i = (blockIdx.x * blockDim.x + threadIdx.x) * 4;
  if (i >= n) return;
  float4 v = *(const float4*)(in + i);
  __nv_bfloat16 h0 = __float2bfloat16_rn(v.x);
  __nv_bfloat16 h1 = __float2bfloat16_rn(v.y);
  __nv_bfloat16 h2 = __float2bfloat16_rn(v.z);
  __nv_bfloat16 h3 = __float2bfloat16_rn(v.w);
  __nv_bfloat16 l0 = __float2bfloat16_rn(v.x - __bfloat162float(h0));
  __nv_bfloat16 l1 = __float2bfloat16_rn(v.y - __bfloat162float(h1));
  __nv_bfloat16 l2 = __float2bfloat16_rn(v.z - __bfloat162float(h2));
  __nv_bfloat16 l3 = __float2bfloat16_rn(v.w - __bfloat162float(h3));
  union { __nv_bfloat16 b[4]; uint2 u; } H, L;
  H.b[0] = h0; H.b[1] = h1; H.b[2] = h2; H.b[3] = h3;
  L.b[0] = l0; L.b[1] = l1; L.b[2] = l2; L.b[3] = l3;
  *(uint2*)(hi + i) = H.u;
  *(uint2*)(lo + i) = L.u;
}

// ---------------------------------------------------------------------------
// TF32 GEMM (round-5 proven version): C[m,n] = sum_k A[m,k]*W[n,k] (+bias)
// Raw fp32 inputs; cvt.rna.tf32 in-register. CTA 128x128, BK=32,
// 8 warps of 64x32, double-buffered cp.async, 2 CTAs/SM.
// ---------------------------------------------------------------------------
#define BKT 32
#define NCHT (HID / BKT)          // 64
#define TSTRT 36                  // floats per smem row
#define TELEMT (128 * TSTRT)      // floats per tile
#define GEMM_T_SMEM (2 * 2 * TELEMT * 4)   // 73728 bytes

__global__ __launch_bounds__(256, 2) void gemm_tf32(
    const float* __restrict__ A, const float* __restrict__ W,
    const float* __restrict__ bias, float* __restrict__ C) {
  extern __shared__ float smf[];
  const uint32_t sbase = smem_u32(smf);
  const int tid  = threadIdx.x;
  const int wid  = tid >> 5;
  const int lane = tid & 31;
  const int bm = blockIdx.y << 7;
  const int bn = blockIdx.x << 7;
  const int warp_m = (wid & 1) << 6;   // 0 or 64
  const int warp_n = (wid >> 1) << 5;  // 0,32,64,96

  const float* gp[2] = {A + (size_t)bm * HID, W + (size_t)bn * HID};

  auto issue_chunk = [&](int c) {
    const int p = c & 1;
    const int k0 = c * BKT;
    const uint32_t s0 = sbase + p * 2 * TELEMT * 4;
#pragma unroll
    for (int t = 0; t < 2; t++) {
#pragma unroll
      for (int i = 0; i < 4; i++) {
        int u = tid + (i << 8);
        int row = u >> 3;
        int g = (u & 7) << 2;
        const float* ga = gp[t] + (size_t)row * HID + k0 + g;
        uint32_t sa = s0 + (t * TELEMT + row * TSTRT + g) * 4;
        CP_ASYNC16(sa, ga);
      }
    }
    CP_COMMIT();
  };

  float acc[4][4][4];
#pragma unroll
  for (int mt = 0; mt < 4; mt++)
#pragma unroll
    for (int nt = 0; nt < 4; nt++)
#pragma unroll
      for (int r = 0; r < 4; r++) acc[mt][nt][r] = 0.f;

  issue_chunk(0);

  for (int c = 0; c < NCHT; c++) {
    if (c + 1 < NCHT) { issue_chunk(c + 1); CP_WAIT1(); }
    else              { CP_WAIT0(); }
    __syncthreads();

    const float* sA = smf + (c & 1) * 2 * TELEMT;
    const float* sB = sA + TELEMT;

#pragma unroll
    for (int ks = 0; ks < 4; ks++) {
      const int kc = ks << 3;
      uint32_t a[4][4];
      const int r0 = warp_m + (lane >> 2);
      const int ca = kc + (lane & 3);
#pragma unroll
      for (int mt = 0; mt < 4; mt++) {
        const int rr = r0 + (mt << 4);
        a[mt][0] = f2tf32(sA[rr * TSTRT + ca]);
        a[mt][1] = f2tf32(sA[(rr + 8) * TSTRT + ca]);
        a[mt][2] = f2tf32(sA[rr * TSTRT + ca + 4]);
        a[mt][3] = f2tf32(sA[(rr + 8) * TSTRT + ca + 4]);
      }
      uint32_t b[4][2];
      const int n0 = warp_n + (lane >> 2);
      const int cb = kc + (lane & 3);
#pragma unroll
      for (int nt = 0; nt < 4; nt++) {
        const int nn = n0 + (nt << 3);
        b[nt][0] = f2tf32(sB[nn * TSTRT + cb]);
        b[nt][1] = f2tf32(sB[nn * TSTRT + cb + 4]);
      }
#pragma unroll
      for (int mt = 0; mt < 4; mt++)
#pragma unroll
        for (int nt = 0; nt < 4; nt++)
          mma1688_tf32(acc[mt][nt], a[mt], b[nt]);
    }
    __syncthreads();
  }

  const int r  = lane >> 2;
  const int c2 = (lane & 3) << 1;
#pragma unroll
  for (int mt = 0; mt < 4; mt++) {
    const int row0 = bm + warp_m + (mt << 4) + r;
#pragma unroll
    for (int nt = 0; nt < 4; nt++) {
      const int col = bn + warp_n + (nt << 3) + c2;
      float b0 = 0.f, b1 = 0.f;
      if (bias) { b0 = bias[col]; b1 = bias[col + 1]; }
      float2 v0 = {acc[mt][nt][0] + b0, acc[mt][nt][1] + b1};
      float2 v1 = {acc[mt][nt][2] + b0, acc[mt][nt][3] + b1};
      *(float2*)&C[(size_t)row0 * HID + col]       = v0;
      *(float2*)&C[(size_t)(row0 + 8) * HID + col] = v1;
    }
  }
}

// ---------------------------------------------------------------------------
// RoPE + bf16 hi/lo split. q gets scale*log2(e) folded in.
// ---------------------------------------------------------------------------
__global__ void rope_split(const float* __restrict__ q, const float* __restrict__ k,
                           const float* __restrict__ cosb, const float* __restrict__ sinb,
                           __nv_bfloat16* __restrict__ qhi, __nv_bfloat16* __restrict__ qlo,
                           __nv_bfloat16* __restrict__ khi, __nv_bfloat16* __restrict__ klo)
{
  const float SC = 0.08838834764831845f * 1.4426950408889634f;
  int i = blockIdx.x * blockDim.x + threadIdx.x;
  int d  = i & 63;
  int h  = (i >> 6) & 15;
  int ms = i >> 10;
  int s  = ms & (S_LEN - 1);
  size_t base = (size_t)ms * HID + (size_t)h * HD;

  float c1 = cosb[s * HD + d],      s1 = sinb[s * HD + d];
  float c2 = cosb[s * HD + d + 64], s2 = sinb[s * HD + d + 64];

  float q1 = q[base + d], q2 = q[base + d + 64];
  float qa = (q1 * c1 - q2 * s1) * SC;
  float qb = (q2 * c2 + q1 * s2) * SC;
  float k1 = k[base + d], k2 = k[base + d + 64];
  float ka = k1 * c1 - k2 * s1;
  float kb = k2 * c2 + k1 * s2;

  __nv_bfloat16 t;
  t = __float2bfloat16_rn(qa); qhi[base + d]      = t; qlo[base + d]      = __float2bfloat16_rn(qa - __bfloat162float(t));
  t = __float2bfloat16_rn(qb); qhi[base + d + 64] = t; qlo[base + d + 64] = __float2bfloat16_rn(qb - __bfloat162float(t));
  t = __float2bfloat16_rn(ka); khi[base + d]      = t; klo[base + d]      = __float2bfloat16_rn(ka - __bfloat162float(t));
  t = __float2bfloat16_rn(kb); khi[base + d + 64] = t; klo[base + d + 64] = __float2bfloat16_rn(kb - __bfloat162float(t));
}

// ---------------------------------------------------------------------------
// HMMA flash attention, bf16x3, exp2-domain softmax.
// Deferred-PV software pipeline: iteration t runs QK(t), then PV(t-1)
// (independent of softmax(t)), then softmax(t); Oa-rescale after PV(t-1).
// kv chunks of 32 rows, 4 smem stages, cp.async commit t+2 / wait_group 1.
// ---------------------------------------------------------------------------
#define ASTR 136
#define QT_ELEM (128 * ASTR)
#define KV_ROWS 32
#define KV_ELEM (KV_ROWS * ASTR)
#define STAGE_ELEM (4 * KV_ELEM)
#define NSTAGE 4
#define A_SMEM ((2 * QT_ELEM + NSTAGE * STAGE_ELEM) * 2)  // 208896 bytes

__global__ __launch_bounds__(256, 1) void attn_mma(
    const __nv_bfloat16* __restrict__ qhi, const __nv_bfloat16* __restrict__ qlo,
    const __nv_bfloat16* __restrict__ khi, const __nv_bfloat16* __restrict__ klo,
    const __nv_bfloat16* __restrict__ vhi, const __nv_bfloat16* __restrict__ vlo,
    float* __restrict__ O)
{
  extern __shared__ __nv_bfloat16 sma[];
  const uint32_t sb = smem_u32(sma);
  const int tid  = threadIdx.x;
  const int wid  = tid >> 5;
  const int lane = tid & 31;
  const int q0 = blockIdx.x << 7;
  const int b  = blockIdx.y >> 4;
  const int h  = blockIdx.y & 15;
  const int warp_m = wid << 4;

  const size_t bS = (size_t)b * S_LEN;
  const size_t h128 = (size_t)h * HD;

  const uint32_t sQhi = sb;
  const uint32_t sQlo = sb + QT_ELEM * 2;
  const uint32_t sKV0 = sb + 2 * QT_ELEM * 2;

  // ---- Q load (part of cp.async group 0)
#pragma unroll
  for (int i = 0; i < 8; i++) {
    int u = tid + (i << 8);
    int row = u >> 4, c8 = (u & 15) << 3;
    size_t g = (bS + q0 + row) * HID + h128 + c8;
    uint32_t so = (uint32_t)(row * ASTR + c8) * 2;
    CP_ASYNC16(sQhi + so, qhi + g);
    CP_ASYNC16(sQlo + so, qlo + g);
  }
  auto issue_kv = [&](int t) {
    const uint32_t bufb = sKV0 + (uint32_t)(t & 3) * (STAGE_ELEM * 2);
    const int kv0 = t << 5;
#pragma unroll
    for (int i = 0; i < 2; i++) {
      int u = tid + (i << 8);
      int row = u >> 4, c8 = (u & 15) << 3;
      size_t g = (bS + kv0 + row) * HID + h128 + c8;
      uint32_t so = (uint32_t)(row * ASTR + c8) * 2;
      CP_ASYNC16(bufb + so,                   khi + g);
      CP_ASYNC16(bufb + KV_ELEM * 2 + so,     klo + g);
      CP_ASYNC16(bufb + 2 * KV_ELEM * 2 + so, vhi + g);
      CP_ASYNC16(bufb + 3 * KV_ELEM * 2 + so, vlo + g);
    }
    CP_COMMIT();
  };
  issue_kv(0);   // group 0 (includes Q)
  issue_kv(1);   // group 1

  float m0 = -1e30f, m1 = -1e30f, l0 = 0.f, l1 = 0.f;
  float Oa[16][4];
#pragma unroll
  for (int j = 0; j < 16; j++)
#pragma unroll
    for (int r = 0; r < 4; r++) Oa[j][r] = 0.f;

  uint32_t ph[4][2], pl[4][2];   // P fragments (previous tile, consumed by PV)

  // PV of tile pt (reads stage pt&3, uses ph/pl as currently held)
  auto do_pv = [&](int pt) {
    const uint32_t pb = sKV0 + (uint32_t)(pt & 3) * (STAGE_ELEM * 2);
    const uint32_t sVhi = pb + 2 * KV_ELEM * 2;
    const uint32_t sVlo = pb + 3 * KV_ELEM * 2;
#pragma unroll
    for (int kk = 0; kk < 2; kk++) {
      uint32_t paH[4] = {ph[kk*2][0], ph[kk*2][1], ph[kk*2+1][0], ph[kk*2+1][1]};
      uint32_t paL[4] = {pl[kk*2][0], pl[kk*2][1], pl[kk*2+1][0], pl[kk*2+1][1]};
#pragma unroll
      for (int dp = 0; dp < 8; dp++) {
        uint32_t bH[4], bL[4];
        const uint32_t voff =
            (uint32_t)(((kk << 4) + (lane & 7) + (((lane >> 3) & 1) << 3)) * ASTR
                       + (dp << 4) + ((lane >> 4) << 3)) * 2;
        ldsm4t(sVhi + voff, bH[0], bH[1], bH[2], bH[3]);
        ldsm4t(sVlo + voff, bL[0], bL[1], bL[2], bL[3]);
        mma16816(Oa[dp * 2],     paH, bH);
        mma16816(Oa[dp * 2],     paH, bL);
        mma16816(Oa[dp * 2],     paL, bH);
        mma16816(Oa[dp * 2 + 1], paH, bH + 2);
        mma16816(Oa[dp * 2 + 1], paH, bL + 2);
        mma16816(Oa[dp * 2 + 1], paL, bH + 2);
      }
    }
  };

  const int NT = S_LEN / KV_ROWS;   // 64
  for (int t = 0; t < NT; t++) {
    if (t < NT - 1) CP_WAIT1(); else CP_WAIT0();
    __syncthreads();           // stage t visible; stage (t-2) fully consumed
    if (t + 2 < NT) issue_kv(t + 2);

    const uint32_t buf  = sKV0 + (uint32_t)(t & 3) * (STAGE_ELEM * 2);
    const uint32_t sKhi = buf;
    const uint32_t sKlo = buf + KV_ELEM * 2;

    // ---- QK(t): S tile 16 x 32
    float S[4][4];
#pragma unroll
    for (int j = 0; j < 4; j++)
#pragma unroll
      for (int r = 0; r < 4; r++) S[j][r] = 0.f;

#pragma unroll
    for (int kc = 0; kc < 8; kc++) {
      uint32_t aH[4], aL[4];
      const uint32_t qoff =
          (uint32_t)((warp_m + (lane & 15)) * ASTR + (kc << 4) + ((lane >> 4) << 3)) * 2;
      ldsm4(sQhi + qoff, aH[0], aH[1], aH[2], aH[3]);
      ldsm4(sQlo + qoff, aL[0], aL[1], aL[2], aL[3]);
#pragma unroll
      for (int np = 0; np < 2; np++) {
        uint32_t bH[4], bL[4];
        const uint32_t koff =
            (uint32_t)(((np << 4) + (lane & 7) + (((lane >> 4) & 1) << 3)) * ASTR
                       + (kc << 4) + (((lane >> 3) & 1) << 3)) * 2;
        ldsm4(sKhi + koff, bH[0], bH[1], bH[2], bH[3]);
        ldsm4(sKlo + koff, bL[0], bL[1], bL[2], bL[3]);
        mma16816(S[np * 2],     aH, bH);
        mma16816(S[np * 2],     aH, bL);
        mma16816(S[np * 2],     aL, bH);
        mma16816(S[np * 2 + 1], aH, bH + 2);
        mma16816(S[np * 2 + 1], aH, bL + 2);
        mma16816(S[np * 2 + 1], aL, bH + 2);
      }
    }

    // ---- PV(t-1): independent of softmax(t); fills the MMA pipe while the
    // softmax below (which ptxas hoists into this stream) resolves.
    if (t > 0) do_pv(t - 1);

    // ---- softmax(t) (exp2 domain): max, exp2, pack new P; rescale AFTER PV
    float mx0 = m0, mx1 = m1;
#pragma unroll
    for (int j = 0; j < 4; j++) {
      mx0 = fmaxf(mx0, fmaxf(S[j][0], S[j][1]));
      mx1 = fmaxf(mx1, fmaxf(S[j][2], S[j][3]));
    }
    mx0 = fmaxf(mx0, __shfl_xor_sync(0xffffffffu, mx0, 1));
    mx0 = fmaxf(mx0, __shfl_xor_sync(0xffffffffu, mx0, 2));
    mx1 = fmaxf(mx1, __shfl_xor_sync(0xffffffffu, mx1, 1));
    mx1 = fmaxf(mx1, __shfl_xor_sync(0xffffffffu, mx1, 2));
    const float al0 = exp2p(m0 - mx0);
    const float al1 = exp2p(m1 - mx1);
    m0 = mx0; m1 = mx1;

    float sum0 = 0.f, sum1 = 0.f;
#pragma unroll
    for (int j = 0; j < 4; j++) {
      float p00 = exp2p(S[j][0] - mx0);
      float p01 = exp2p(S[j][1] - mx0);
      float p10 = exp2p(S[j][2] - mx1);
      float p11 = exp2p(S[j][3] - mx1);
      sum0 += p00 + p01;
      sum1 += p10 + p11;
      float h00 = __bfloat162float(__float2bfloat16_rn(p00));
      float h01 = __bfloat162float(__float2bfloat16_rn(p01));
      float h10 = __bfloat162float(__float2bfloat16_rn(p10));
      float h11 = __bfloat162float(__float2bfloat16_rn(p11));
      ph[j][0] = pack_bf16(h00, h01);
      ph[j][1] = pack_bf16(h10, h11);
      pl[j][0] = pack_bf16(p00 - h00, p01 - h01);
      pl[j][1] = pack_bf16(p10 - h10, p11 - h11);
    }
    l0 = l0 * al0 + sum0;
    l1 = l1 * al1 + sum1;

    // rescale Oa into the new max scale (must follow PV(t-1))
#pragma unroll
    for (int j = 0; j < 16; j++) {
      Oa[j][0] *= al0; Oa[j][1] *= al0;
      Oa[j][2] *= al1; Oa[j][3] *= al1;
    }
  }

  // ---- tail: PV of the last tile
  do_pv(NT - 1);

  // ---- epilogue
  l0 += __shfl_xor_sync(0xffffffffu, l0, 1);
  l0 += __shfl_xor_sync(0xffffffffu, l0, 2);
  l1 += __shfl_xor_sync(0xffffffffu, l1, 1);
  l1 += __shfl_xor_sync(0xffffffffu, l1, 2);
  const float inv0 = 1.f / l0;
  const float inv1 = 1.f / l1;
  const int row0 = q0 + warp_m + (lane >> 2);
  const int cofs = (lane & 3) << 1;
#pragma unroll
  for (int j = 0; j < 16; j++) {
    const int col = (j << 3) + cofs;
    float2 v0 = {Oa[j][0] * inv0, Oa[j][1] * inv0};
    float2 v1 = {Oa[j][2] * inv1, Oa[j][3] * inv1};
    *(float2*)&O[(bS + row0) * HID + h128 + col]     = v0;
    *(float2*)&O[(bS + row0 + 8) * HID + h128 + col] = v1;
  }
}

// ---------------------------------------------------------------------------
extern "C" void kernel_launch(void* const* d_in, const int* in_sizes, int n_in,
                              void* d_out, int out_size)
{
  (void)in_sizes; (void)n_in; (void)out_size;
  const float* x    = (const float*)d_in[0];
  const float* cosb = (const float*)d_in[1];
  const float* sinb = (const float*)d_in[2];
  const float* wq   = (const float*)d_in[3];
  const float* bq   = (const float*)d_in[4];
  const float* wk   = (const float*)d_in[5];
  const float* bk   = (const float*)d_in[6];
  const float* wv   = (const float*)d_in[7];
  const float* bv   = (const float*)d_in[8];
  const float* wo   = (const float*)d_in[9];
  float* out = (float*)d_out;

  float *q, *k, *v, *ao;
  cudaGetSymbolAddress((void**)&q,  g_q);
  cudaGetSymbolAddress((void**)&k,  g_k);
  cudaGetSymbolAddress((void**)&v,  g_v);
  cudaGetSymbolAddress((void**)&ao, g_ao);

  __nv_bfloat16 *qhi, *qlo, *khi, *klo, *vhi, *vlo;
  cudaGetSymbolAddress((void**)&qhi, g_qhi);
  cudaGetSymbolAddress((void**)&qlo, g_qlo);
  cudaGetSymbolAddress((void**)&khi, g_khi);
  cudaGetSymbolAddress((void**)&klo, g_klo);
  cudaGetSymbolAddress((void**)&vhi, g_vhi);
  cudaGetSymbolAddress((void**)&vlo, g_vlo);

  static bool attrs_set = false;
  if (!attrs_set) {
    cudaFuncSetAttribute(gemm_tf32,
                         cudaFuncAttributeMaxDynamicSharedMemorySize, GEMM_T_SMEM);
    cudaFuncSetAttribute(attn_mma,
                         cudaFuncAttributeMaxDynamicSharedMemorySize, A_SMEM);
    attrs_set = true;
  }

  const int NX = MROWS * HID;

  dim3 gg(HID / 128, MROWS / 128);  // (16, 32)
  gemm_tf32<<<gg, 256, GEMM_T_SMEM>>>(x,  wq, bq, q);
  gemm_tf32<<<gg, 256, GEMM_T_SMEM>>>(x,  wk, bk, k);
  gemm_tf32<<<gg, 256, GEMM_T_SMEM>>>(x,  wv, bv, v);

  rope_split<<<(MROWS * NH * 64) / 256, 256>>>(q, k, cosb, sinb, qhi, qlo, khi, klo);
  cvt_split<<<NX / 1024, 256>>>(v, vhi, vlo, NX);

  attn_mma<<<dim3(S_LEN / 128, BATCH * NH), 256, A_SMEM>>>(qhi, qlo, khi, klo, vhi, vlo, ao);

  gemm_tf32<<<gg, 256, GEMM_T_SMEM>>>(ao, wo, nullptr, out);
}

// round 8
// speedup vs baseline: 1.0197x; 1.0197x over previous
#include <cuda_runtime.h>
#include <cuda_bf16.h>
#include <cstdint>
#include <cstddef>

#define S_LEN 2048
#define HID   2048
#define NH    16
#define HD    128
#define BATCH 2
#define MROWS (BATCH * S_LEN)

// ---------------------------------------------------------------------------
// Scratch (allocation-free rule: device globals)
// ---------------------------------------------------------------------------
__device__ float g_q [(size_t)MROWS * HID];
__device__ float g_k [(size_t)MROWS * HID];
__device__ float g_v [(size_t)MROWS * HID];
__device__ float g_ao[(size_t)MROWS * HID];

__device__ __nv_bfloat16 g_qhi[(size_t)MROWS * HID];
__device__ __nv_bfloat16 g_qlo[(size_t)MROWS * HID];
__device__ __nv_bfloat16 g_khi[(size_t)MROWS * HID];
__device__ __nv_bfloat16 g_klo[(size_t)MROWS * HID];
__device__ __nv_bfloat16 g_vhi[(size_t)MROWS * HID];
__device__ __nv_bfloat16 g_vlo[(size_t)MROWS * HID];

// ---------------------------------------------------------------------------
// helpers
// ---------------------------------------------------------------------------
__device__ __forceinline__ uint32_t smem_u32(const void* p) {
  uint32_t a;
  asm("{ .reg .u64 t; cvta.to.shared.u64 t, %1; cvt.u32.u64 %0, t; }"
      : "=r"(a) : "l"(p));
  return a;
}

__device__ __forceinline__ void ldsm4(uint32_t addr, uint32_t& r0, uint32_t& r1,
                                      uint32_t& r2, uint32_t& r3) {
  asm volatile("ldmatrix.sync.aligned.m8n8.x4.shared.b16 {%0,%1,%2,%3}, [%4];"
               : "=r"(r0), "=r"(r1), "=r"(r2), "=r"(r3) : "r"(addr));
}

__device__ __forceinline__ void ldsm4t(uint32_t addr, uint32_t& r0, uint32_t& r1,
                                       uint32_t& r2, uint32_t& r3) {
  asm volatile("ldmatrix.sync.aligned.m8n8.x4.trans.shared.b16 {%0,%1,%2,%3}, [%4];"
               : "=r"(r0), "=r"(r1), "=r"(r2), "=r"(r3) : "r"(addr));
}

__device__ __forceinline__ void mma16816(float* d, const uint32_t* a,
                                         const uint32_t* b) {
  asm volatile(
      "mma.sync.aligned.m16n8k16.row.col.f32.bf16.bf16.f32 "
      "{%0,%1,%2,%3}, {%4,%5,%6,%7}, {%8,%9}, {%0,%1,%2,%3};"
      : "+f"(d[0]), "+f"(d[1]), "+f"(d[2]), "+f"(d[3])
      : "r"(a[0]), "r"(a[1]), "r"(a[2]), "r"(a[3]), "r"(b[0]), "r"(b[1]));
}

__device__ __forceinline__ void mma1688_tf32(float* d, const uint32_t* a,
                                             const uint32_t* b) {
  asm volatile(
      "mma.sync.aligned.m16n8k8.row.col.f32.tf32.tf32.f32 "
      "{%0,%1,%2,%3}, {%4,%5,%6,%7}, {%8,%9}, {%0,%1,%2,%3};"
      : "+f"(d[0]), "+f"(d[1]), "+f"(d[2]), "+f"(d[3])
      : "r"(a[0]), "r"(a[1]), "r"(a[2]), "r"(a[3]), "r"(b[0]), "r"(b[1]));
}

__device__ __forceinline__ uint32_t f2tf32(float x) {
  uint32_t r;
  asm("cvt.rna.tf32.f32 %0, %1;" : "=r"(r) : "f"(x));
  return r;
}

#define CP_ASYNC16(saddr, gaddr) \
  asm volatile("cp.async.cg.shared.global [%0], [%1], 16;" \
               :: "r"(saddr), "l"(gaddr))
#define CP_COMMIT() asm volatile("cp.async.commit_group;")
#define CP_WAIT1()  asm volatile("cp.async.wait_group 1;")
#define CP_WAIT0()  asm volatile("cp.async.wait_group 0;")

// FFMA-only exp2 (no MUFU): magic-round + degree-6 Taylor, |err| < 2e-7.
__device__ __forceinline__ float exp2p(float x) {
  x = fmaxf(x, -126.f);
  float r = x + 12582912.f;
  int   e = __float_as_int(r) - 0x4B400000;
  float f = x - (r - 12582912.f);
  float p = 1.5403e-4f;
  p = fmaf(p, f, 1.3333558e-3f);
  p = fmaf(p, f, 9.6181291e-3f);
  p = fmaf(p, f, 5.5504109e-2f);
  p = fmaf(p, f, 2.4022651e-1f);
  p = fmaf(p, f, 6.9314718e-1f);
  p = fmaf(p, f, 1.0f);
  return __int_as_float(__float_as_int(p) + (e << 23));
}

__device__ __forceinline__ uint32_t pack_bf16(float x, float y) {
  __nv_bfloat162 t = __floats2bfloat162_rn(x, y);
  return *(uint32_t*)&t;
}

// ---------------------------------------------------------------------------
// fp32 -> bf16 hi/lo split (used for V)
// ---------------------------------------------------------------------------
__global__ void cvt_split(const float* __restrict__ in,
                          __nv_bfloat16* __restrict__ hi,
                          __nv_bfloat16* __restrict__ lo, int n) {
  int i = (blockIdx.x * blockDim.x + threadIdx.x) * 4;
  if (i >= n) return;
  float4 v = *(const float4*)(in + i);
  __nv_bfloat16 h0 = __float2bfloat16_rn(v.x);
  __nv_bfloat16 h1 = __float2bfloat16_rn(v.y);
  __nv_bfloat16 h2 = __float2bfloat16_rn(v.z);
  __nv_bfloat16 h3 = __float2bfloat16_rn(v.w);
  __nv_bfloat16 l0 = __float2bfloat16_rn(v.x - __bfloat162float(h0));
  __nv_bfloat16 l1 = __float2bfloat16_rn(v.y - __bfloat162float(h1));
  __nv_bfloat16 l2 = __float2bfloat16_rn(v.z - __bfloat162float(h2));
  __nv_bfloat16 l3 = __float2bfloat16_rn(v.w - __bfloat162float(h3));
  union { __nv_bfloat16 b[4]; uint2 u; } H, L;
  H.b[0] = h0; H.b[1] = h1; H.b[2] = h2; H.b[3] = h3;
  L.b[0] = l0; L.b[1] = l1; L.b[2] = l2; L.b[3] = l3;
  *(uint2*)(hi + i) = H.u;
  *(uint2*)(lo + i) = L.u;
}

// ---------------------------------------------------------------------------
// TF32 GEMM (round-5 proven version): C[m,n] = sum_k A[m,k]*W[n,k] (+bias)
// ---------------------------------------------------------------------------
#define BKT 32
#define NCHT (HID / BKT)
#define TSTRT 36
#define TELEMT (128 * TSTRT)
#define GEMM_T_SMEM (2 * 2 * TELEMT * 4)

__global__ __launch_bounds__(256, 2) void gemm_tf32(
    const float* __restrict__ A, const float* __restrict__ W,
    const float* __restrict__ bias, float* __restrict__ C) {
  extern __shared__ float smf[];
  const uint32_t sbase = smem_u32(smf);
  const int tid  = threadIdx.x;
  const int wid  = tid >> 5;
  const int lane = tid & 31;
  const int bm = blockIdx.y << 7;
  const int bn = blockIdx.x << 7;
  const int warp_m = (wid & 1) << 6;
  const int warp_n = (wid >> 1) << 5;

  const float* gp[2] = {A + (size_t)bm * HID, W + (size_t)bn * HID};

  auto issue_chunk = [&](int c) {
    const int p = c & 1;
    const int k0 = c * BKT;
    const uint32_t s0 = sbase + p * 2 * TELEMT * 4;
#pragma unroll
    for (int t = 0; t < 2; t++) {
#pragma unroll
      for (int i = 0; i < 4; i++) {
        int u = tid + (i << 8);
        int row = u >> 3;
        int g = (u & 7) << 2;
        const float* ga = gp[t] + (size_t)row * HID + k0 + g;
        uint32_t sa = s0 + (t * TELEMT + row * TSTRT + g) * 4;
        CP_ASYNC16(sa, ga);
      }
    }
    CP_COMMIT();
  };

  float acc[4][4][4];
#pragma unroll
  for (int mt = 0; mt < 4; mt++)
#pragma unroll
    for (int nt = 0; nt < 4; nt++)
#pragma unroll
      for (int r = 0; r < 4; r++) acc[mt][nt][r] = 0.f;

  issue_chunk(0);

  for (int c = 0; c < NCHT; c++) {
    if (c + 1 < NCHT) { issue_chunk(c + 1); CP_WAIT1(); }
    else              { CP_WAIT0(); }
    __syncthreads();

    const float* sA = smf + (c & 1) * 2 * TELEMT;
    const float* sB = sA + TELEMT;

#pragma unroll
    for (int ks = 0; ks < 4; ks++) {
      const int kc = ks << 3;
      uint32_t a[4][4];
      const int r0 = warp_m + (lane >> 2);
      const int ca = kc + (lane & 3);
#pragma unroll
      for (int mt = 0; mt < 4; mt++) {
        const int rr = r0 + (mt << 4);
        a[mt][0] = f2tf32(sA[rr * TSTRT + ca]);
        a[mt][1] = f2tf32(sA[(rr + 8) * TSTRT + ca]);
        a[mt][2] = f2tf32(sA[rr * TSTRT + ca + 4]);
        a[mt][3] = f2tf32(sA[(rr + 8) * TSTRT + ca + 4]);
      }
      uint32_t b[4][2];
      const int n0 = warp_n + (lane >> 2);
      const int cb = kc + (lane & 3);
#pragma unroll
      for (int nt = 0; nt < 4; nt++) {
        const int nn = n0 + (nt << 3);
        b[nt][0] = f2tf32(sB[nn * TSTRT + cb]);
        b[nt][1] = f2tf32(sB[nn * TSTRT + cb + 4]);
      }
#pragma unroll
      for (int mt = 0; mt < 4; mt++)
#pragma unroll
        for (int nt = 0; nt < 4; nt++)
          mma1688_tf32(acc[mt][nt], a[mt], b[nt]);
    }
    __syncthreads();
  }

  const int r  = lane >> 2;
  const int c2 = (lane & 3) << 1;
#pragma unroll
  for (int mt = 0; mt < 4; mt++) {
    const int row0 = bm + warp_m + (mt << 4) + r;
#pragma unroll
    for (int nt = 0; nt < 4; nt++) {
      const int col = bn + warp_n + (nt << 3) + c2;
      float b0 = 0.f, b1 = 0.f;
      if (bias) { b0 = bias[col]; b1 = bias[col + 1]; }
      float2 v0 = {acc[mt][nt][0] + b0, acc[mt][nt][1] + b1};
      float2 v1 = {acc[mt][nt][2] + b0, acc[mt][nt][3] + b1};
      *(float2*)&C[(size_t)row0 * HID + col]       = v0;
      *(float2*)&C[(size_t)(row0 + 8) * HID + col] = v1;
    }
  }
}

// ---------------------------------------------------------------------------
// RoPE + bf16 hi/lo split. q gets scale*log2(e) folded in.
// ---------------------------------------------------------------------------
__global__ void rope_split(const float* __restrict__ q, const float* __restrict__ k,
                           const float* __restrict__ cosb, const float* __restrict__ sinb,
                           __nv_bfloat16* __restrict__ qhi, __nv_bfloat16* __restrict__ qlo,
                           __nv_bfloat16* __restrict__ khi, __nv_bfloat16* __restrict__ klo)
{
  const float SC = 0.08838834764831845f * 1.4426950408889634f;
  int i = blockIdx.x * blockDim.x + threadIdx.x;
  int d  = i & 63;
  int h  = (i >> 6) & 15;
  int ms = i >> 10;
  int s  = ms & (S_LEN - 1);
  size_t base = (size_t)ms * HID + (size_t)h * HD;

  float c1 = cosb[s * HD + d],      s1 = sinb[s * HD + d];
  float c2 = cosb[s * HD + d + 64], s2 = sinb[s * HD + d + 64];

  float q1 = q[base + d], q2 = q[base + d + 64];
  float qa = (q1 * c1 - q2 * s1) * SC;
  float qb = (q2 * c2 + q1 * s2) * SC;
  float k1 = k[base + d], k2 = k[base + d + 64];
  float ka = k1 * c1 - k2 * s1;
  float kb = k2 * c2 + k1 * s2;

  __nv_bfloat16 t;
  t = __float2bfloat16_rn(qa); qhi[base + d]      = t; qlo[base + d]      = __float2bfloat16_rn(qa - __bfloat162float(t));
  t = __float2bfloat16_rn(qb); qhi[base + d + 64] = t; qlo[base + d + 64] = __float2bfloat16_rn(qb - __bfloat162float(t));
  t = __float2bfloat16_rn(ka); khi[base + d]      = t; klo[base + d]      = __float2bfloat16_rn(ka - __bfloat162float(t));
  t = __float2bfloat16_rn(kb); khi[base + d + 64] = t; klo[base + d + 64] = __float2bfloat16_rn(kb - __bfloat162float(t));
}

// ---------------------------------------------------------------------------
// HMMA flash attention, bf16x3, exp2 softmax, 64-row kv tiles.
// Q-hi fragments in REGISTERS (one-time LDG); Q-lo single smem array.
// K double-buffered, V triple-buffered; PV(t-1) deferred between QK(t)
// and softmax(t) so softmax FFMA/shuffle latency hides behind PV MMAs.
// ---------------------------------------------------------------------------
#define ASTR 136
#define QLO_ELEM (128 * ASTR)            // 17408
#define KV_ROWS 64
#define KV_ELEM (KV_ROWS * ASTR)         // 8704
#define KSTAGE (2 * KV_ELEM)             // hi+lo per K stage
#define VSTAGE (2 * KV_ELEM)             // hi+lo per V stage
#define A_SMEM ((QLO_ELEM + 2 * KSTAGE + 3 * VSTAGE) * 2)  // 208896 bytes

__global__ __launch_bounds__(256, 1) void attn_mma(
    const __nv_bfloat16* __restrict__ qhi, const __nv_bfloat16* __restrict__ qlo,
    const __nv_bfloat16* __restrict__ khi, const __nv_bfloat16* __restrict__ klo,
    const __nv_bfloat16* __restrict__ vhi, const __nv_bfloat16* __restrict__ vlo,
    float* __restrict__ O)
{
  extern __shared__ __nv_bfloat16 sma[];
  const uint32_t sb = smem_u32(sma);
  const int tid  = threadIdx.x;
  const int wid  = tid >> 5;
  const int lane = tid & 31;
  const int q0 = blockIdx.x << 7;
  const int b  = blockIdx.y >> 4;
  const int h  = blockIdx.y & 15;
  const int warp_m = wid << 4;

  const size_t bS = (size_t)b * S_LEN;
  const size_t h128 = (size_t)h * HD;

  const uint32_t sQlo = sb;
  const uint32_t sK0  = sb + QLO_ELEM * 2;
  const uint32_t sV0  = sK0 + 2 * KSTAGE * 2;

  // ---- Q-hi fragments straight to registers (ldsm-compatible layout)
  uint32_t aHq[8][4];
  {
    const int r0 = warp_m + (lane >> 2);
    const int c0 = (lane & 3) << 1;
    const size_t gbase = (bS + q0 + r0) * HID + h128 + c0;
#pragma unroll
    for (int kc = 0; kc < 8; kc++) {
      const size_t g = gbase + (kc << 4);
      aHq[kc][0] = *(const uint32_t*)(qhi + g);
      aHq[kc][1] = *(const uint32_t*)(qhi + g + 8 * HID);
      aHq[kc][2] = *(const uint32_t*)(qhi + g + 8);
      aHq[kc][3] = *(const uint32_t*)(qhi + g + 8 * HID + 8);
    }
  }

  // ---- Q-lo into smem (rides with cp.async group 0)
#pragma unroll
  for (int i = 0; i < 8; i++) {
    int u = tid + (i << 8);
    int row = u >> 4, c8 = (u & 15) << 3;
    size_t g = (bS + q0 + row) * HID + h128 + c8;
    CP_ASYNC16(sQlo + (uint32_t)(row * ASTR + c8) * 2, qlo + g);
  }

  auto issue_kv = [&](int t) {
    const uint32_t kb = sK0 + (uint32_t)(t & 1) * (KSTAGE * 2);
    const uint32_t vb = sV0 + (uint32_t)(t % 3) * (VSTAGE * 2);
    const int kv0 = t << 6;
#pragma unroll
    for (int i = 0; i < 4; i++) {
      int u = tid + (i << 8);
      int row = u >> 4, c8 = (u & 15) << 3;
      size_t g = (bS + kv0 + row) * HID + h128 + c8;
      uint32_t so = (uint32_t)(row * ASTR + c8) * 2;
      CP_ASYNC16(kb + so,               khi + g);
      CP_ASYNC16(kb + KV_ELEM * 2 + so, klo + g);
      CP_ASYNC16(vb + so,               vhi + g);
      CP_ASYNC16(vb + KV_ELEM * 2 + so, vlo + g);
    }
    CP_COMMIT();
  };
  issue_kv(0);   // group 0 (includes Q-lo)
  issue_kv(1);   // group 1

  float m0 = -1e30f, m1 = -1e30f, l0 = 0.f, l1 = 0.f;
  float Oa[16][4];
#pragma unroll
  for (int j = 0; j < 16; j++)
#pragma unroll
    for (int r = 0; r < 4; r++) Oa[j][r] = 0.f;

  uint32_t ph[8][2], pl[8][2];   // P fragments of the previous tile

  auto do_pv = [&](int pt) {
    const uint32_t vb = sV0 + (uint32_t)(pt % 3) * (VSTAGE * 2);
    const uint32_t sVhi = vb;
    const uint32_t sVlo = vb + KV_ELEM * 2;
#pragma unroll
    for (int kk = 0; kk < 4; kk++) {
      uint32_t paH[4] = {ph[kk*2][0], ph[kk*2][1], ph[kk*2+1][0], ph[kk*2+1][1]};
      uint32_t paL[4] = {pl[kk*2][0], pl[kk*2][1], pl[kk*2+1][0], pl[kk*2+1][1]};
#pragma unroll
      for (int dp = 0; dp < 8; dp++) {
        uint32_t bH[4], bL[4];
        const uint32_t voff =
            (uint32_t)(((kk << 4) + (lane & 7) + (((lane >> 3) & 1) << 3)) * ASTR
                       + (dp << 4) + ((lane >> 4) << 3)) * 2;
        ldsm4t(sVhi + voff, bH[0], bH[1], bH[2], bH[3]);
        ldsm4t(sVlo + voff, bL[0], bL[1], bL[2], bL[3]);
        mma16816(Oa[dp * 2],     paH, bH);
        mma16816(Oa[dp * 2],     paH, bL);
        mma16816(Oa[dp * 2],     paL, bH);
        mma16816(Oa[dp * 2 + 1], paH, bH + 2);
        mma16816(Oa[dp * 2 + 1], paH, bL + 2);
        mma16816(Oa[dp * 2 + 1], paL, bH + 2);
      }
    }
  };

  const int NT = S_LEN / KV_ROWS;   // 32
  for (int t = 0; t < NT; t++) {
    if (t < NT - 1) CP_WAIT1(); else CP_WAIT0();
    __syncthreads();   // stage t visible; all warps past prior compute

    const uint32_t kb = sK0 + (uint32_t)(t & 1) * (KSTAGE * 2);
    const uint32_t sKhi = kb;
    const uint32_t sKlo = kb + KV_ELEM * 2;

    // ---- QK(t)
    float S[8][4];
#pragma unroll
    for (int j = 0; j < 8; j++)
#pragma unroll
      for (int r = 0; r < 4; r++) S[j][r] = 0.f;

#pragma unroll
    for (int kc = 0; kc < 8; kc++) {
      uint32_t aL[4];
      const uint32_t qoff =
          (uint32_t)((warp_m + (lane & 15)) * ASTR + (kc << 4) + ((lane >> 4) << 3)) * 2;
      ldsm4(sQlo + qoff, aL[0], aL[1], aL[2], aL[3]);
#pragma unroll
      for (int np = 0; np < 4; np++) {
        uint32_t bH[4], bL[4];
        const uint32_t koff =
            (uint32_t)(((np << 4) + (lane & 7) + (((lane >> 4) & 1) << 3)) * ASTR
                       + (kc << 4) + (((lane >> 3) & 1) << 3)) * 2;
        ldsm4(sKhi + koff, bH[0], bH[1], bH[2], bH[3]);
        ldsm4(sKlo + koff, bL[0], bL[1], bL[2], bL[3]);
        mma16816(S[np * 2],     aHq[kc], bH);
        mma16816(S[np * 2],     aHq[kc], bL);
        mma16816(S[np * 2],     aL,      bH);
        mma16816(S[np * 2 + 1], aHq[kc], bH + 2);
        mma16816(S[np * 2 + 1], aHq[kc], bL + 2);
        mma16816(S[np * 2 + 1], aL,      bH + 2);
      }
    }

    // ---- PV(t-1): independent MMA stream that hides softmax(t) latency
    if (t > 0) do_pv(t - 1);

    // ---- softmax(t) (exp2 domain); Oa-rescale AFTER PV(t-1)
    float mx0 = m0, mx1 = m1;
#pragma unroll
    for (int j = 0; j < 8; j++) {
      mx0 = fmaxf(mx0, fmaxf(S[j][0], S[j][1]));
      mx1 = fmaxf(mx1, fmaxf(S[j][2], S[j][3]));
    }
    mx0 = fmaxf(mx0, __shfl_xor_sync(0xffffffffu, mx0, 1));
    mx0 = fmaxf(mx0, __shfl_xor_sync(0xffffffffu, mx0, 2));
    mx1 = fmaxf(mx1, __shfl_xor_sync(0xffffffffu, mx1, 1));
    mx1 = fmaxf(mx1, __shfl_xor_sync(0xffffffffu, mx1, 2));
    const float al0 = exp2p(m0 - mx0);
    const float al1 = exp2p(m1 - mx1);
    m0 = mx0; m1 = mx1;

    float sum0 = 0.f, sum1 = 0.f;
#pragma unroll
    for (int j = 0; j < 8; j++) {
      float p00 = exp2p(S[j][0] - mx0);
      float p01 = exp2p(S[j][1] - mx0);
      float p10 = exp2p(S[j][2] - mx1);
      float p11 = exp2p(S[j][3] - mx1);
      sum0 += p00 + p01;
      sum1 += p10 + p11;
      float h00 = __bfloat162float(__float2bfloat16_rn(p00));
      float h01 = __bfloat162float(__float2bfloat16_rn(p01));
      float h10 = __bfloat162float(__float2bfloat16_rn(p10));
      float h11 = __bfloat162float(__float2bfloat16_rn(p11));
      ph[j][0] = pack_bf16(h00, h01);
      ph[j][1] = pack_bf16(h10, h11);
      pl[j][0] = pack_bf16(p00 - h00, p01 - h01);
      pl[j][1] = pack_bf16(p10 - h10, p11 - h11);
    }
    l0 = l0 * al0 + sum0;
    l1 = l1 * al1 + sum1;
#pragma unroll
    for (int j = 0; j < 16; j++) {
      Oa[j][0] *= al0; Oa[j][1] *= al0;
      Oa[j][2] *= al1; Oa[j][3] *= al1;
    }

    __syncthreads();   // all warps done with K(t) and V(t-1) slots
    if (t + 2 < NT) issue_kv(t + 2);
  }

  // ---- tail PV
  do_pv(NT - 1);

  // ---- epilogue
  l0 += __shfl_xor_sync(0xffffffffu, l0, 1);
  l0 += __shfl_xor_sync(0xffffffffu, l0, 2);
  l1 += __shfl_xor_sync(0xffffffffu, l1, 1);
  l1 += __shfl_xor_sync(0xffffffffu, l1, 2);
  const float inv0 = 1.f / l0;
  const float inv1 = 1.f / l1;
  const int row0 = q0 + warp_m + (lane >> 2);
  const int cofs = (lane & 3) << 1;
#pragma unroll
  for (int j = 0; j < 16; j++) {
    const int col = (j << 3) + cofs;
    float2 v0 = {Oa[j][0] * inv0, Oa[j][1] * inv0};
    float2 v1 = {Oa[j][2] * inv1, Oa[j][3] * inv1};
    *(float2*)&O[(bS + row0) * HID + h128 + col]     = v0;
    *(float2*)&O[(bS + row0 + 8) * HID + h128 + col] = v1;
  }
}

// ---------------------------------------------------------------------------
extern "C" void kernel_launch(void* const* d_in, const int* in_sizes, int n_in,
                              void* d_out, int out_size)
{
  (void)in_sizes; (void)n_in; (void)out_size;
  const float* x    = (const float*)d_in[0];
  const float* cosb = (const float*)d_in[1];
  const float* sinb = (const float*)d_in[2];
  const float* wq   = (const float*)d_in[3];
  const float* bq   = (const float*)d_in[4];
  const float* wk   = (const float*)d_in[5];
  const float* bk   = (const float*)d_in[6];
  const float* wv   = (const float*)d_in[7];
  const float* bv   = (const float*)d_in[8];
  const float* wo   = (const float*)d_in[9];
  float* out = (float*)d_out;

  float *q, *k, *v, *ao;
  cudaGetSymbolAddress((void**)&q,  g_q);
  cudaGetSymbolAddress((void**)&k,  g_k);
  cudaGetSymbolAddress((void**)&v,  g_v);
  cudaGetSymbolAddress((void**)&ao, g_ao);

  __nv_bfloat16 *qhi, *qlo, *khi, *klo, *vhi, *vlo;
  cudaGetSymbolAddress((void**)&qhi, g_qhi);
  cudaGetSymbolAddress((void**)&qlo, g_qlo);
  cudaGetSymbolAddress((void**)&khi, g_khi);
  cudaGetSymbolAddress((void**)&klo, g_klo);
  cudaGetSymbolAddress((void**)&vhi, g_vhi);
  cudaGetSymbolAddress((void**)&vlo, g_vlo);

  static bool attrs_set = false;
  if (!attrs_set) {
    cudaFuncSetAttribute(gemm_tf32,
                         cudaFuncAttributeMaxDynamicSharedMemorySize, GEMM_T_SMEM);
    cudaFuncSetAttribute(attn_mma,
                         cudaFuncAttributeMaxDynamicSharedMemorySize, A_SMEM);
    attrs_set = true;
  }

  const int NX = MROWS * HID;

  dim3 gg(HID / 128, MROWS / 128);  // (16, 32)
  gemm_tf32<<<gg, 256, GEMM_T_SMEM>>>(x,  wq, bq, q);
  gemm_tf32<<<gg, 256, GEMM_T_SMEM>>>(x,  wk, bk, k);
  gemm_tf32<<<gg, 256, GEMM_T_SMEM>>>(x,  wv, bv, v);

  rope_split<<<(MROWS * NH * 64) / 256, 256>>>(q, k, cosb, sinb, qhi, qlo, khi, klo);
  cvt_split<<<NX / 1024, 256>>>(v, vhi, vlo, NX);

  attn_mma<<<dim3(S_LEN / 128, BATCH * NH), 256, A_SMEM>>>(qhi, qlo, khi, klo, vhi, vlo, ao);

  gemm_tf32<<<gg, 256, GEMM_T_SMEM>>>(ao, wo, nullptr, out);
}

// round 9
// speedup vs baseline: 1.0749x; 1.0542x over previous
#include <cuda_runtime.h>
#include <cuda_bf16.h>
#include <cstdint>
#include <cstddef>

#define S_LEN 2048
#define HID   2048
#define NH    16
#define HD    128
#define BATCH 2
#define MROWS (BATCH * S_LEN)

// ---------------------------------------------------------------------------
// Scratch (allocation-free rule: device globals)
// ---------------------------------------------------------------------------
__device__ float g_q [(size_t)MROWS * HID];
__device__ float g_k [(size_t)MROWS * HID];
__device__ float g_v [(size_t)MROWS * HID];
__device__ float g_ao[(size_t)MROWS * HID];

__device__ __nv_bfloat16 g_qhi[(size_t)MROWS * HID];
__device__ __nv_bfloat16 g_qlo[(size_t)MROWS * HID];
__device__ __nv_bfloat16 g_khi[(size_t)MROWS * HID];
__device__ __nv_bfloat16 g_klo[(size_t)MROWS * HID];
__device__ __nv_bfloat16 g_vhi[(size_t)MROWS * HID];
__device__ __nv_bfloat16 g_vlo[(size_t)MROWS * HID];

// ---------------------------------------------------------------------------
// helpers
// ---------------------------------------------------------------------------
__device__ __forceinline__ uint32_t smem_u32(const void* p) {
  uint32_t a;
  asm("{ .reg .u64 t; cvta.to.shared.u64 t, %1; cvt.u32.u64 %0, t; }"
      : "=r"(a) : "l"(p));
  return a;
}

__device__ __forceinline__ void ldsm4(uint32_t addr, uint32_t& r0, uint32_t& r1,
                                      uint32_t& r2, uint32_t& r3) {
  asm volatile("ldmatrix.sync.aligned.m8n8.x4.shared.b16 {%0,%1,%2,%3}, [%4];"
               : "=r"(r0), "=r"(r1), "=r"(r2), "=r"(r3) : "r"(addr));
}

__device__ __forceinline__ void ldsm4t(uint32_t addr, uint32_t& r0, uint32_t& r1,
                                       uint32_t& r2, uint32_t& r3) {
  asm volatile("ldmatrix.sync.aligned.m8n8.x4.trans.shared.b16 {%0,%1,%2,%3}, [%4];"
               : "=r"(r0), "=r"(r1), "=r"(r2), "=r"(r3) : "r"(addr));
}

__device__ __forceinline__ void mma16816(float* d, const uint32_t* a,
                                         const uint32_t* b) {
  asm volatile(
      "mma.sync.aligned.m16n8k16.row.col.f32.bf16.bf16.f32 "
      "{%0,%1,%2,%3}, {%4,%5,%6,%7}, {%8,%9}, {%0,%1,%2,%3};"
      : "+f"(d[0]), "+f"(d[1]), "+f"(d[2]), "+f"(d[3])
      : "r"(a[0]), "r"(a[1]), "r"(a[2]), "r"(a[3]), "r"(b[0]), "r"(b[1]));
}

__device__ __forceinline__ void mma1688_tf32(float* d, const uint32_t* a,
                                             const uint32_t* b) {
  asm volatile(
      "mma.sync.aligned.m16n8k8.row.col.f32.tf32.tf32.f32 "
      "{%0,%1,%2,%3}, {%4,%5,%6,%7}, {%8,%9}, {%0,%1,%2,%3};"
      : "+f"(d[0]), "+f"(d[1]), "+f"(d[2]), "+f"(d[3])
      : "r"(a[0]), "r"(a[1]), "r"(a[2]), "r"(a[3]), "r"(b[0]), "r"(b[1]));
}

__device__ __forceinline__ uint32_t f2tf32(float x) {
  uint32_t r;
  asm("cvt.rna.tf32.f32 %0, %1;" : "=r"(r) : "f"(x));
  return r;
}

#define CP_ASYNC16(saddr, gaddr) \
  asm volatile("cp.async.cg.shared.global [%0], [%1], 16;" \
               :: "r"(saddr), "l"(gaddr))
#define CP_COMMIT() asm volatile("cp.async.commit_group;")
#define CP_WAIT1()  asm volatile("cp.async.wait_group 1;")
#define CP_WAIT0()  asm volatile("cp.async.wait_group 0;")

// FFMA-only exp2 (no MUFU): magic-round + degree-6 Taylor, |err| < 2e-7.
__device__ __forceinline__ float exp2p(float x) {
  x = fmaxf(x, -126.f);
  float r = x + 12582912.f;
  int   e = __float_as_int(r) - 0x4B400000;
  float f = x - (r - 12582912.f);
  float p = 1.5403e-4f;
  p = fmaf(p, f, 1.3333558e-3f);
  p = fmaf(p, f, 9.6181291e-3f);
  p = fmaf(p, f, 5.5504109e-2f);
  p = fmaf(p, f, 2.4022651e-1f);
  p = fmaf(p, f, 6.9314718e-1f);
  p = fmaf(p, f, 1.0f);
  return __int_as_float(__float_as_int(p) + (e << 23));
}

__device__ __forceinline__ uint32_t pack_bf16(float x, float y) {
  __nv_bfloat162 t = __floats2bfloat162_rn(x, y);
  return *(uint32_t*)&t;
}

// ---------------------------------------------------------------------------
// fp32 -> bf16 hi/lo split (used for V)
// ---------------------------------------------------------------------------
__global__ void cvt_split(const float* __restrict__ in,
                          __nv_bfloat16* __restrict__ hi,
                          __nv_bfloat16* __restrict__ lo, int n) {
  int i = (blockIdx.x * blockDim.x + threadIdx.x) * 4;
  if (i >= n) return;
  float4 v = *(const float4*)(in + i);
  __nv_bfloat16 h0 = __float2bfloat16_rn(v.x);
  __nv_bfloat16 h1 = __float2bfloat16_rn(v.y);
  __nv_bfloat16 h2 = __float2bfloat16_rn(v.z);
  __nv_bfloat16 h3 = __float2bfloat16_rn(v.w);
  __nv_bfloat16 l0 = __float2bfloat16_rn(v.x - __bfloat162float(h0));
  __nv_bfloat16 l1 = __float2bfloat16_rn(v.y - __bfloat162float(h1));
  __nv_bfloat16 l2 = __float2bfloat16_rn(v.z - __bfloat162float(h2));
  __nv_bfloat16 l3 = __float2bfloat16_rn(v.w - __bfloat162float(h3));
  union { __nv_bfloat16 b[4]; uint2 u; } H, L;
  H.b[0] = h0; H.b[1] = h1; H.b[2] = h2; H.b[3] = h3;
  L.b[0] = l0; L.b[1] = l1; L.b[2] = l2; L.b[3] = l3;
  *(uint2*)(hi + i) = H.u;
  *(uint2*)(lo + i) = L.u;
}

// ---------------------------------------------------------------------------
// TF32 GEMM (round-5 proven version): C[m,n] = sum_k A[m,k]*W[n,k] (+bias)
// ---------------------------------------------------------------------------
#define BKT 32
#define NCHT (HID / BKT)
#define TSTRT 36
#define TELEMT (128 * TSTRT)
#define GEMM_T_SMEM (2 * 2 * TELEMT * 4)

__global__ __launch_bounds__(256, 2) void gemm_tf32(
    const float* __restrict__ A, const float* __restrict__ W,
    const float* __restrict__ bias, float* __restrict__ C) {
  extern __shared__ float smf[];
  const uint32_t sbase = smem_u32(smf);
  const int tid  = threadIdx.x;
  const int wid  = tid >> 5;
  const int lane = tid & 31;
  const int bm = blockIdx.y << 7;
  const int bn = blockIdx.x << 7;
  const int warp_m = (wid & 1) << 6;
  const int warp_n = (wid >> 1) << 5;

  const float* gp[2] = {A + (size_t)bm * HID, W + (size_t)bn * HID};

  auto issue_chunk = [&](int c) {
    const int p = c & 1;
    const int k0 = c * BKT;
    const uint32_t s0 = sbase + p * 2 * TELEMT * 4;
#pragma unroll
    for (int t = 0; t < 2; t++) {
#pragma unroll
      for (int i = 0; i < 4; i++) {
        int u = tid + (i << 8);
        int row = u >> 3;
        int g = (u & 7) << 2;
        const float* ga = gp[t] + (size_t)row * HID + k0 + g;
        uint32_t sa = s0 + (t * TELEMT + row * TSTRT + g) * 4;
        CP_ASYNC16(sa, ga);
      }
    }
    CP_COMMIT();
  };

  float acc[4][4][4];
#pragma unroll
  for (int mt = 0; mt < 4; mt++)
#pragma unroll
    for (int nt = 0; nt < 4; nt++)
#pragma unroll
      for (int r = 0; r < 4; r++) acc[mt][nt][r] = 0.f;

  issue_chunk(0);

  for (int c = 0; c < NCHT; c++) {
    if (c + 1 < NCHT) { issue_chunk(c + 1); CP_WAIT1(); }
    else              { CP_WAIT0(); }
    __syncthreads();

    const float* sA = smf + (c & 1) * 2 * TELEMT;
    const float* sB = sA + TELEMT;

#pragma unroll
    for (int ks = 0; ks < 4; ks++) {
      const int kc = ks << 3;
      uint32_t a[4][4];
      const int r0 = warp_m + (lane >> 2);
      const int ca = kc + (lane & 3);
#pragma unroll
      for (int mt = 0; mt < 4; mt++) {
        const int rr = r0 + (mt << 4);
        a[mt][0] = f2tf32(sA[rr * TSTRT + ca]);
        a[mt][1] = f2tf32(sA[(rr + 8) * TSTRT + ca]);
        a[mt][2] = f2tf32(sA[rr * TSTRT + ca + 4]);
        a[mt][3] = f2tf32(sA[(rr + 8) * TSTRT + ca + 4]);
      }
      uint32_t b[4][2];
      const int n0 = warp_n + (lane >> 2);
      const int cb = kc + (lane & 3);
#pragma unroll
      for (int nt = 0; nt < 4; nt++) {
        const int nn = n0 + (nt << 3);
        b[nt][0] = f2tf32(sB[nn * TSTRT + cb]);
        b[nt][1] = f2tf32(sB[nn * TSTRT + cb + 4]);
      }
#pragma unroll
      for (int mt = 0; mt < 4; mt++)
#pragma unroll
        for (int nt = 0; nt < 4; nt++)
          mma1688_tf32(acc[mt][nt], a[mt], b[nt]);
    }
    __syncthreads();
  }

  const int r  = lane >> 2;
  const int c2 = (lane & 3) << 1;
#pragma unroll
  for (int mt = 0; mt < 4; mt++) {
    const int row0 = bm + warp_m + (mt << 4) + r;
#pragma unroll
    for (int nt = 0; nt < 4; nt++) {
      const int col = bn + warp_n + (nt << 3) + c2;
      float b0 = 0.f, b1 = 0.f;
      if (bias) { b0 = bias[col]; b1 = bias[col + 1]; }
      float2 v0 = {acc[mt][nt][0] + b0, acc[mt][nt][1] + b1};
      float2 v1 = {acc[mt][nt][2] + b0, acc[mt][nt][3] + b1};
      *(float2*)&C[(size_t)row0 * HID + col]       = v0;
      *(float2*)&C[(size_t)(row0 + 8) * HID + col] = v1;
    }
  }
}

// ---------------------------------------------------------------------------
// RoPE + bf16 hi/lo split. q gets scale*log2(e) folded in.
// ---------------------------------------------------------------------------
__global__ void rope_split(const float* __restrict__ q, const float* __restrict__ k,
                           const float* __restrict__ cosb, const float* __restrict__ sinb,
                           __nv_bfloat16* __restrict__ qhi, __nv_bfloat16* __restrict__ qlo,
                           __nv_bfloat16* __restrict__ khi, __nv_bfloat16* __restrict__ klo)
{
  const float SC = 0.08838834764831845f * 1.4426950408889634f;
  int i = blockIdx.x * blockDim.x + threadIdx.x;
  int d  = i & 63;
  int h  = (i >> 6) & 15;
  int ms = i >> 10;
  int s  = ms & (S_LEN - 1);
  size_t base = (size_t)ms * HID + (size_t)h * HD;

  float c1 = cosb[s * HD + d],      s1 = sinb[s * HD + d];
  float c2 = cosb[s * HD + d + 64], s2 = sinb[s * HD + d + 64];

  float q1 = q[base + d], q2 = q[base + d + 64];
  float qa = (q1 * c1 - q2 * s1) * SC;
  float qb = (q2 * c2 + q1 * s2) * SC;
  float k1 = k[base + d], k2 = k[base + d + 64];
  float ka = k1 * c1 - k2 * s1;
  float kb = k2 * c2 + k1 * s2;

  __nv_bfloat16 t;
  t = __float2bfloat16_rn(qa); qhi[base + d]      = t; qlo[base + d]      = __float2bfloat16_rn(qa - __bfloat162float(t));
  t = __float2bfloat16_rn(qb); qhi[base + d + 64] = t; qlo[base + d + 64] = __float2bfloat16_rn(qb - __bfloat162float(t));
  t = __float2bfloat16_rn(ka); khi[base + d]      = t; klo[base + d]      = __float2bfloat16_rn(ka - __bfloat162float(t));
  t = __float2bfloat16_rn(kb); khi[base + d + 64] = t; klo[base + d + 64] = __float2bfloat16_rn(kb - __bfloat162float(t));
}

// ---------------------------------------------------------------------------
// HMMA flash attention, bf16x3, exp2 softmax — 2 CTAs/SM version.
// CTA: 64 q-rows, 4 warps (128 threads), warp = 16 q-rows.
// Q-hi fragments in registers (one-time LDG); Q-lo in smem.
// K/V hi+lo double-buffered 32-row tiles. 85 KB smem -> 2 CTAs/SM: the
// second resident CTA's MMAs cover this CTA's barrier/softmax stalls.
// ---------------------------------------------------------------------------
#define ASTR 136
#define Q_ROWS 64
#define QLO_ELEM (Q_ROWS * ASTR)            // 8704 elems
#define KV_ROWS 32
#define KV_ELEM (KV_ROWS * ASTR)            // 4352 elems
#define STAGE_ELEM (4 * KV_ELEM)            // Khi,Klo,Vhi,Vlo
#define A_SMEM ((QLO_ELEM + 2 * STAGE_ELEM) * 2)   // 87040 bytes

__global__ __launch_bounds__(128, 2) void attn_mma(
    const __nv_bfloat16* __restrict__ qhi, const __nv_bfloat16* __restrict__ qlo,
    const __nv_bfloat16* __restrict__ khi, const __nv_bfloat16* __restrict__ klo,
    const __nv_bfloat16* __restrict__ vhi, const __nv_bfloat16* __restrict__ vlo,
    float* __restrict__ O)
{
  extern __shared__ __nv_bfloat16 sma[];
  const uint32_t sb = smem_u32(sma);
  const int tid  = threadIdx.x;
  const int wid  = tid >> 5;
  const int lane = tid & 31;
  const int q0 = blockIdx.x << 6;          // 64 q-rows per CTA
  const int b  = blockIdx.y >> 4;
  const int h  = blockIdx.y & 15;
  const int warp_m = wid << 4;             // 0,16,32,48

  const size_t bS = (size_t)b * S_LEN;
  const size_t h128 = (size_t)h * HD;

  const uint32_t sQlo = sb;
  const uint32_t sKV0 = sb + QLO_ELEM * 2;

  // ---- Q-hi fragments straight to registers (ldsm-compatible layout)
  uint32_t aHq[8][4];
  {
    const int r0 = warp_m + (lane >> 2);
    const int c0 = (lane & 3) << 1;
    const size_t gbase = (bS + q0 + r0) * HID + h128 + c0;
#pragma unroll
    for (int kc = 0; kc < 8; kc++) {
      const size_t g = gbase + (kc << 4);
      aHq[kc][0] = *(const uint32_t*)(qhi + g);
      aHq[kc][1] = *(const uint32_t*)(qhi + g + 8 * HID);
      aHq[kc][2] = *(const uint32_t*)(qhi + g + 8);
      aHq[kc][3] = *(const uint32_t*)(qhi + g + 8 * HID + 8);
    }
  }

  // ---- Q-lo into smem (rides with cp.async group 0)
#pragma unroll
  for (int i = 0; i < 8; i++) {
    int u = tid + (i << 7);
    int row = u >> 4, c8 = (u & 15) << 3;
    size_t g = (bS + q0 + row) * HID + h128 + c8;
    CP_ASYNC16(sQlo + (uint32_t)(row * ASTR + c8) * 2, qlo + g);
  }

  auto issue_kv = [&](int t) {
    const uint32_t bufb = sKV0 + (uint32_t)(t & 1) * (STAGE_ELEM * 2);
    const int kv0 = t << 5;
#pragma unroll
    for (int i = 0; i < 4; i++) {
      int u = tid + (i << 7);
      int row = u >> 4, c8 = (u & 15) << 3;
      size_t g = (bS + kv0 + row) * HID + h128 + c8;
      uint32_t so = (uint32_t)(row * ASTR + c8) * 2;
      CP_ASYNC16(bufb + so,                   khi + g);
      CP_ASYNC16(bufb + KV_ELEM * 2 + so,     klo + g);
      CP_ASYNC16(bufb + 2 * KV_ELEM * 2 + so, vhi + g);
      CP_ASYNC16(bufb + 3 * KV_ELEM * 2 + so, vlo + g);
    }
    CP_COMMIT();
  };
  issue_kv(0);   // group 0 (includes Q-lo)
  issue_kv(1);   // group 1

  float m0 = -1e30f, m1 = -1e30f, l0 = 0.f, l1 = 0.f;
  float Oa[16][4];
#pragma unroll
  for (int j = 0; j < 16; j++)
#pragma unroll
    for (int r = 0; r < 4; r++) Oa[j][r] = 0.f;

  const int NT = S_LEN / KV_ROWS;   // 64
  for (int t = 0; t < NT; t++) {
    if (t < NT - 1) CP_WAIT1(); else CP_WAIT0();
    __syncthreads();

    const uint32_t buf  = sKV0 + (uint32_t)(t & 1) * (STAGE_ELEM * 2);
    const uint32_t sKhi = buf;
    const uint32_t sKlo = buf + KV_ELEM * 2;
    const uint32_t sVhi = buf + 2 * KV_ELEM * 2;
    const uint32_t sVlo = buf + 3 * KV_ELEM * 2;

    // ---- QK(t): 16 x 32 scores
    float S[4][4];
#pragma unroll
    for (int j = 0; j < 4; j++)
#pragma unroll
      for (int r = 0; r < 4; r++) S[j][r] = 0.f;

#pragma unroll
    for (int kc = 0; kc < 8; kc++) {
      uint32_t aL[4];
      const uint32_t qoff =
          (uint32_t)((warp_m + (lane & 15)) * ASTR + (kc << 4) + ((lane >> 4) << 3)) * 2;
      ldsm4(sQlo + qoff, aL[0], aL[1], aL[2], aL[3]);
#pragma unroll
      for (int np = 0; np < 2; np++) {
        uint32_t bH[4], bL[4];
        const uint32_t koff =
            (uint32_t)(((np << 4) + (lane & 7) + (((lane >> 4) & 1) << 3)) * ASTR
                       + (kc << 4) + (((lane >> 3) & 1) << 3)) * 2;
        ldsm4(sKhi + koff, bH[0], bH[1], bH[2], bH[3]);
        ldsm4(sKlo + koff, bL[0], bL[1], bL[2], bL[3]);
        mma16816(S[np * 2],     aHq[kc], bH);
        mma16816(S[np * 2],     aHq[kc], bL);
        mma16816(S[np * 2],     aL,      bH);
        mma16816(S[np * 2 + 1], aHq[kc], bH + 2);
        mma16816(S[np * 2 + 1], aHq[kc], bL + 2);
        mma16816(S[np * 2 + 1], aL,      bH + 2);
      }
    }

    // ---- softmax(t) (exp2 domain)
    float mx0 = m0, mx1 = m1;
#pragma unroll
    for (int j = 0; j < 4; j++) {
      mx0 = fmaxf(mx0, fmaxf(S[j][0], S[j][1]));
      mx1 = fmaxf(mx1, fmaxf(S[j][2], S[j][3]));
    }
    mx0 = fmaxf(mx0, __shfl_xor_sync(0xffffffffu, mx0, 1));
    mx0 = fmaxf(mx0, __shfl_xor_sync(0xffffffffu, mx0, 2));
    mx1 = fmaxf(mx1, __shfl_xor_sync(0xffffffffu, mx1, 1));
    mx1 = fmaxf(mx1, __shfl_xor_sync(0xffffffffu, mx1, 2));
    const float al0 = exp2p(m0 - mx0);
    const float al1 = exp2p(m1 - mx1);
    m0 = mx0; m1 = mx1;

    uint32_t ph[4][2], pl[4][2];
    float sum0 = 0.f, sum1 = 0.f;
#pragma unroll
    for (int j = 0; j < 4; j++) {
      float p00 = exp2p(S[j][0] - mx0);
      float p01 = exp2p(S[j][1] - mx0);
      float p10 = exp2p(S[j][2] - mx1);
      float p11 = exp2p(S[j][3] - mx1);
      sum0 += p00 + p01;
      sum1 += p10 + p11;
      float h00 = __bfloat162float(__float2bfloat16_rn(p00));
      float h01 = __bfloat162float(__float2bfloat16_rn(p01));
      float h10 = __bfloat162float(__float2bfloat16_rn(p10));
      float h11 = __bfloat162float(__float2bfloat16_rn(p11));
      ph[j][0] = pack_bf16(h00, h01);
      ph[j][1] = pack_bf16(h10, h11);
      pl[j][0] = pack_bf16(p00 - h00, p01 - h01);
      pl[j][1] = pack_bf16(p10 - h10, p11 - h11);
    }
    l0 = l0 * al0 + sum0;
    l1 = l1 * al1 + sum1;
#pragma unroll
    for (int j = 0; j < 16; j++) {
      Oa[j][0] *= al0; Oa[j][1] *= al0;
      Oa[j][2] *= al1; Oa[j][3] *= al1;
    }

    // ---- PV(t)
#pragma unroll
    for (int kk = 0; kk < 2; kk++) {
      uint32_t paH[4] = {ph[kk*2][0], ph[kk*2][1], ph[kk*2+1][0], ph[kk*2+1][1]};
      uint32_t paL[4] = {pl[kk*2][0], pl[kk*2][1], pl[kk*2+1][0], pl[kk*2+1][1]};
#pragma unroll
      for (int dp = 0; dp < 8; dp++) {
        uint32_t bH[4], bL[4];
        const uint32_t voff =
            (uint32_t)(((kk << 4) + (lane & 7) + (((lane >> 3) & 1) << 3)) * ASTR
                       + (dp << 4) + ((lane >> 4) << 3)) * 2;
        ldsm4t(sVhi + voff, bH[0], bH[1], bH[2], bH[3]);
        ldsm4t(sVlo + voff, bL[0], bL[1], bL[2], bL[3]);
        mma16816(Oa[dp * 2],     paH, bH);
        mma16816(Oa[dp * 2],     paH, bL);
        mma16816(Oa[dp * 2],     paL, bH);
        mma16816(Oa[dp * 2 + 1], paH, bH + 2);
        mma16816(Oa[dp * 2 + 1], paH, bL + 2);
        mma16816(Oa[dp * 2 + 1], paL, bH + 2);
      }
    }

    __syncthreads();
    if (t + 2 < NT) issue_kv(t + 2);
  }

  // ---- epilogue
  l0 += __shfl_xor_sync(0xffffffffu, l0, 1);
  l0 += __shfl_xor_sync(0xffffffffu, l0, 2);
  l1 += __shfl_xor_sync(0xffffffffu, l1, 1);
  l1 += __shfl_xor_sync(0xffffffffu, l1, 2);
  const float inv0 = 1.f / l0;
  const float inv1 = 1.f / l1;
  const int row0 = q0 + warp_m + (lane >> 2);
  const int cofs = (lane & 3) << 1;
#pragma unroll
  for (int j = 0; j < 16; j++) {
    const int col = (j << 3) + cofs;
    float2 v0 = {Oa[j][0] * inv0, Oa[j][1] * inv0};
    float2 v1 = {Oa[j][2] * inv1, Oa[j][3] * inv1};
    *(float2*)&O[(bS + row0) * HID + h128 + col]     = v0;
    *(float2*)&O[(bS + row0 + 8) * HID + h128 + col] = v1;
  }
}

// ---------------------------------------------------------------------------
extern "C" void kernel_launch(void* const* d_in, const int* in_sizes, int n_in,
                              void* d_out, int out_size)
{
  (void)in_sizes; (void)n_in; (void)out_size;
  const float* x    = (const float*)d_in[0];
  const float* cosb = (const float*)d_in[1];
  const float* sinb = (const float*)d_in[2];
  const float* wq   = (const float*)d_in[3];
  const float* bq   = (const float*)d_in[4];
  const float* wk   = (const float*)d_in[5];
  const float* bk   = (const float*)d_in[6];
  const float* wv   = (const float*)d_in[7];
  const float* bv   = (const float*)d_in[8];
  const float* wo   = (const float*)d_in[9];
  float* out = (float*)d_out;

  float *q, *k, *v, *ao;
  cudaGetSymbolAddress((void**)&q,  g_q);
  cudaGetSymbolAddress((void**)&k,  g_k);
  cudaGetSymbolAddress((void**)&v,  g_v);
  cudaGetSymbolAddress((void**)&ao, g_ao);

  __nv_bfloat16 *qhi, *qlo, *khi, *klo, *vhi, *vlo;
  cudaGetSymbolAddress((void**)&qhi, g_qhi);
  cudaGetSymbolAddress((void**)&qlo, g_qlo);
  cudaGetSymbolAddress((void**)&khi, g_khi);
  cudaGetSymbolAddress((void**)&klo, g_klo);
  cudaGetSymbolAddress((void**)&vhi, g_vhi);
  cudaGetSymbolAddress((void**)&vlo, g_vlo);

  static bool attrs_set = false;
  if (!attrs_set) {
    cudaFuncSetAttribute(gemm_tf32,
                         cudaFuncAttributeMaxDynamicSharedMemorySize, GEMM_T_SMEM);
    cudaFuncSetAttribute(attn_mma,
                         cudaFuncAttributeMaxDynamicSharedMemorySize, A_SMEM);
    attrs_set = true;
  }

  const int NX = MROWS * HID;

  dim3 gg(HID / 128, MROWS / 128);  // (16, 32)
  gemm_tf32<<<gg, 256, GEMM_T_SMEM>>>(x,  wq, bq, q);
  gemm_tf32<<<gg, 256, GEMM_T_SMEM>>>(x,  wk, bk, k);
  gemm_tf32<<<gg, 256, GEMM_T_SMEM>>>(x,  wv, bv, v);

  rope_split<<<(MROWS * NH * 64) / 256, 256>>>(q, k, cosb, sinb, qhi, qlo, khi, klo);
  cvt_split<<<NX / 1024, 256>>>(v, vhi, vlo, NX);

  attn_mma<<<dim3(S_LEN / Q_ROWS, BATCH * NH), 128, A_SMEM>>>(qhi, qlo, khi, klo, vhi, vlo, ao);

  gemm_tf32<<<gg, 256, GEMM_T_SMEM>>>(ao, wo, nullptr, out);
}